// round 12
// baseline (speedup 1.0000x reference)
#include <cuda_runtime.h>
#include <cuda_fp16.h>
#include <cstdint>

// QuantumLinear == x @ W_real^T + bias  (magnitude*cos(atan2(i,r)) == r identically;
// weight_imag is dead code).
//
// Round 11: fp16 m16n8k16 single pass with cross-barrier fragment pipeline (R10)
// + PAIRED tiles: one CP_WAIT(0)+__syncthreads per TWO k-tiles (64 barriers vs 128).
// 5 stages stay race-free: in-flight set at pair j = {2j,2j+1 computing, 2j+2 ready,
// 2j+3,2j+4 loading} = 5 distinct buffers. Prep kernel uses 16B stores.

#define M_DIM 8192
#define N_DIM 4096
#define K_DIM 4096

#define BM 128
#define BN 128
#define BK 32                       // fp16 elements per K-tile (64B rows)
#define STAGES 5
#define KTILES (K_DIM / BK)         // 128
#define KPAIRS (KTILES / 2)         // 64

// smem rows: 64B data + 16B pad = 80B stride -> conflict-free ldmatrix
#define ROW_STRIDE 80
#define TILE_BYTES (128 * ROW_STRIDE)          // 10240
#define STAGE_BYTES (2 * TILE_BYTES)           // 20480
#define SMEM_TOTAL (STAGES * STAGE_BYTES)      // 102400 (x2 CTAs = 200KB/SM)

// ---------------- scratch: fp16 copies ----------------
__device__ __half g_xh[(size_t)M_DIM * K_DIM];
__device__ __half g_wh[(size_t)N_DIM * K_DIM];

// ---------------- helpers ----------------
__device__ __forceinline__ uint32_t smem_u32(const void* p) {
    uint32_t a;
    asm("{ .reg .u64 t; cvta.to.shared.u64 t, %1; cvt.u32.u64 %0, t; }" : "=r"(a) : "l"(p));
    return a;
}

__device__ __forceinline__ void cp16(uint32_t dst, const void* src) {
    asm volatile("cp.async.cg.shared.global [%0], [%1], 16;" :: "r"(dst), "l"(src));
}
#define CP_COMMIT() asm volatile("cp.async.commit_group;" ::: "memory")
#define CP_WAIT(n)  asm volatile("cp.async.wait_group %0;" :: "n"(n) : "memory")

__device__ __forceinline__ void ldsm4(uint32_t* r, uint32_t addr) {
    asm volatile("ldmatrix.sync.aligned.m8n8.x4.shared.b16 {%0,%1,%2,%3}, [%4];"
                 : "=r"(r[0]), "=r"(r[1]), "=r"(r[2]), "=r"(r[3]) : "r"(addr));
}

__device__ __forceinline__ void mma16816(float* d, const uint32_t* a,
                                         uint32_t b0, uint32_t b1) {
    asm volatile(
        "mma.sync.aligned.m16n8k16.row.col.f32.f16.f16.f32 "
        "{%0,%1,%2,%3}, {%4,%5,%6,%7}, {%8,%9}, {%0,%1,%2,%3};"
        : "+f"(d[0]), "+f"(d[1]), "+f"(d[2]), "+f"(d[3])
        : "r"(a[0]), "r"(a[1]), "r"(a[2]), "r"(a[3]), "r"(b0), "r"(b1));
}

// ---------------- prep: fused fp32 -> fp16 (rn), 16B stores ----------------
// out 16B-units: X = M*K*2/16, W = N*K*2/16
#define NX16 ((size_t)M_DIM * K_DIM / 8)    // 4194304
#define NW16 ((size_t)N_DIM * K_DIM / 8)    // 2097152

__global__ __launch_bounds__(256)
void to_fp16_fused(const float4* __restrict__ xs, uint4* __restrict__ xd,
                   const float4* __restrict__ ws, uint4* __restrict__ wd)
{
    size_t i = (size_t)blockIdx.x * blockDim.x + threadIdx.x;
    const float4* s;
    uint4* d;
    if (i < NX16) { s = xs + 2 * i;            d = xd + i; }
    else          { size_t j = i - NX16; s = ws + 2 * j; d = wd + j; }
    float4 v0 = s[0];
    float4 v1 = s[1];
    __half2 h0 = __floats2half2_rn(v0.x, v0.y);
    __half2 h1 = __floats2half2_rn(v0.z, v0.w);
    __half2 h2 = __floats2half2_rn(v1.x, v1.y);
    __half2 h3 = __floats2half2_rn(v1.z, v1.w);
    uint4 o;
    o.x = *(uint32_t*)&h0;  o.y = *(uint32_t*)&h1;
    o.z = *(uint32_t*)&h2;  o.w = *(uint32_t*)&h3;
    *d = o;
}

// ---------------- GEMM ----------------
__global__ __launch_bounds__(256, 2)
void qgemm_fp16(const __half* __restrict__ X,   // [M, K] fp16
                const __half* __restrict__ W,   // [N, K] fp16
                const float* __restrict__ bias, // [N]
                float* __restrict__ out)        // [M, N]
{
    extern __shared__ char smem[];
    const uint32_t sb = smem_u32(smem);

    const int tid  = threadIdx.x;
    const int wid  = tid >> 5;
    const int lane = tid & 31;
    const int warpM = wid & 3;      // m offset 32*warpM
    const int warpN = wid >> 2;     // n offset 64*warpN

    // ---- grouped rasterization: 8 m-tiles per group column ----
    const int pid = blockIdx.x;
    const int group_id = pid >> 8;
    const int pid_m = (group_id << 3) + (pid & 7);
    const int pid_n = (pid & 255) >> 3;
    const int bm = pid_m * BM;
    const int bn = pid_n * BN;

    // ---- global load mapping: 2 rows per thread per tile, 16B chunks ----
    const int ldr   = tid >> 2;       // 0..63
    const int chunk = tid & 3;        // 0..3 (16B = 8 halves)
    const size_t aOff0 = (size_t)(bm + ldr) * K_DIM + chunk * 8;
    const size_t aOff1 = aOff0 + (size_t)64 * K_DIM;
    const size_t bOff0 = (size_t)(bn + ldr) * K_DIM + chunk * 8;
    const size_t bOff1 = bOff0 + (size_t)64 * K_DIM;
    const uint32_t sA0 = ldr * ROW_STRIDE + chunk * 16;
    const uint32_t sA1 = sA0 + 64 * ROW_STRIDE;

    // ---- ldmatrix lane bases ----
    const uint32_t aLane = sb +
        (uint32_t)((warpM * 32 + (lane & 15)) * ROW_STRIDE + ((lane >> 4) * 16));
    const uint32_t bLane = sb + TILE_BYTES +
        (uint32_t)((warpN * 64 + (lane & 7) + ((lane & 16) >> 1)) * ROW_STRIDE +
                   (((lane >> 3) & 1) * 16));

    float acc[2][8][4];
    #pragma unroll
    for (int i = 0; i < 2; i++)
        #pragma unroll
        for (int j = 0; j < 8; j++)
            #pragma unroll
            for (int q = 0; q < 4; q++)
                acc[i][j][q] = 0.0f;

    // ---- prologue: issue tiles 0..2 into stages 0..2 ----
    #pragma unroll
    for (int s = 0; s < 3; s++) {
        const int k0 = s * BK;
        const uint32_t st = sb + s * STAGE_BYTES;
        cp16(st + sA0, X + aOff0 + k0);
        cp16(st + sA1, X + aOff1 + k0);
        cp16(st + TILE_BYTES + sA0, W + bOff0 + k0);
        cp16(st + TILE_BYTES + sA1, W + bOff1 + k0);
    }
    CP_COMMIT();

    // fragment slots: A = even slice, B = odd slice of the rotation
    uint32_t arA[2][4], arB[2][4];
    uint32_t brA[4][4], brB[4][4];

    // preload tile0.slice0 into slot A
    CP_WAIT(0);
    __syncthreads();
    ldsm4(arA[0], aLane);
    ldsm4(arA[1], aLane + 16 * ROW_STRIDE);
    #pragma unroll
    for (int p = 0; p < 4; p++)
        ldsm4(brA[p], bLane + p * (16 * ROW_STRIDE));

    uint32_t b0 = 0;   // stage offset of tile 2j

    // ---- main loop: one wait+barrier per TWO tiles ----
    #pragma unroll 1
    for (int j = 0; j < KPAIRS; j++) {
        CP_WAIT(0);          // tiles up to 2j+2 arrived (issued >= 1 pair ago)
        __syncthreads();     // visible to all; buffers of pair j-1 free

        uint32_t b1 = b0 + STAGE_BYTES; if (b1 == SMEM_TOTAL) b1 = 0;
        uint32_t b2 = b1 + STAGE_BYTES; if (b2 == SMEM_TOTAL) b2 = 0;
        uint32_t b3 = b2 + STAGE_BYTES; if (b3 == SMEM_TOTAL) b3 = 0;
        uint32_t b4 = b3 + STAGE_BYTES; if (b4 == SMEM_TOTAL) b4 = 0;

        // issue loads for tiles 2j+3, 2j+4
        const int t3 = 2 * j + 3;
        if (t3 < KTILES) {
            const int k0 = t3 * BK;
            const uint32_t st = sb + b3;
            cp16(st + sA0, X + aOff0 + k0);
            cp16(st + sA1, X + aOff1 + k0);
            cp16(st + TILE_BYTES + sA0, W + bOff0 + k0);
            cp16(st + TILE_BYTES + sA1, W + bOff1 + k0);
        }
        const int t4 = 2 * j + 4;
        if (t4 < KTILES) {
            const int k0 = t4 * BK;
            const uint32_t st = sb + b4;
            cp16(st + sA0, X + aOff0 + k0);
            cp16(st + sA1, X + aOff1 + k0);
            cp16(st + TILE_BYTES + sA0, W + bOff0 + k0);
            cp16(st + TILE_BYTES + sA1, W + bOff1 + k0);
        }
        CP_COMMIT();

        // round 0: ldsm t0.s1 -> B ; mma t0.s0 from A
        ldsm4(arB[0], aLane + b0 + 32);
        ldsm4(arB[1], aLane + b0 + 32 + 16 * ROW_STRIDE);
        #pragma unroll
        for (int p = 0; p < 4; p++)
            ldsm4(brB[p], bLane + b0 + 32 + p * (16 * ROW_STRIDE));
        #pragma unroll
        for (int mt = 0; mt < 2; mt++)
            #pragma unroll
            for (int nt = 0; nt < 8; nt++)
                mma16816(acc[mt][nt], arA[mt],
                         brA[nt >> 1][(nt & 1) * 2], brA[nt >> 1][(nt & 1) * 2 + 1]);

        // round 1: ldsm t1.s0 -> A ; mma t0.s1 from B
        ldsm4(arA[0], aLane + b1);
        ldsm4(arA[1], aLane + b1 + 16 * ROW_STRIDE);
        #pragma unroll
        for (int p = 0; p < 4; p++)
            ldsm4(brA[p], bLane + b1 + p * (16 * ROW_STRIDE));
        #pragma unroll
        for (int mt = 0; mt < 2; mt++)
            #pragma unroll
            for (int nt = 0; nt < 8; nt++)
                mma16816(acc[mt][nt], arB[mt],
                         brB[nt >> 1][(nt & 1) * 2], brB[nt >> 1][(nt & 1) * 2 + 1]);

        // round 2: ldsm t1.s1 -> B ; mma t1.s0 from A
        ldsm4(arB[0], aLane + b1 + 32);
        ldsm4(arB[1], aLane + b1 + 32 + 16 * ROW_STRIDE);
        #pragma unroll
        for (int p = 0; p < 4; p++)
            ldsm4(brB[p], bLane + b1 + 32 + p * (16 * ROW_STRIDE));
        #pragma unroll
        for (int mt = 0; mt < 2; mt++)
            #pragma unroll
            for (int nt = 0; nt < 8; nt++)
                mma16816(acc[mt][nt], arA[mt],
                         brA[nt >> 1][(nt & 1) * 2], brA[nt >> 1][(nt & 1) * 2 + 1]);

        // round 3: ldsm t2.s0 -> A (cross-barrier preload) ; mma t1.s1 from B
        if (j + 1 < KPAIRS) {
            ldsm4(arA[0], aLane + b2);
            ldsm4(arA[1], aLane + b2 + 16 * ROW_STRIDE);
            #pragma unroll
            for (int p = 0; p < 4; p++)
                ldsm4(brA[p], bLane + b2 + p * (16 * ROW_STRIDE));
        }
        #pragma unroll
        for (int mt = 0; mt < 2; mt++)
            #pragma unroll
            for (int nt = 0; nt < 8; nt++)
                mma16816(acc[mt][nt], arB[mt],
                         brB[nt >> 1][(nt & 1) * 2], brB[nt >> 1][(nt & 1) * 2 + 1]);

        b0 = b2;
    }

    // ---- epilogue: direct stores + bias ----
    const int g = lane >> 2;
    const int t = lane & 3;
    #pragma unroll
    for (int mt = 0; mt < 2; mt++) {
        const int row0 = bm + warpM * 32 + mt * 16 + g;
        #pragma unroll
        for (int nt = 0; nt < 8; nt++) {
            const int col = bn + warpN * 64 + nt * 8 + 2 * t;
            const float2 b2v = *(const float2*)(bias + col);
            float2 o0, o1;
            o0.x = acc[mt][nt][0] + b2v.x;
            o0.y = acc[mt][nt][1] + b2v.y;
            o1.x = acc[mt][nt][2] + b2v.x;
            o1.y = acc[mt][nt][3] + b2v.y;
            *(float2*)(out + (size_t)row0 * N_DIM + col)       = o0;
            *(float2*)(out + (size_t)(row0 + 8) * N_DIM + col) = o1;
        }
    }
}

// ---------------- host ----------------
extern "C" void kernel_launch(void* const* d_in, const int* in_sizes, int n_in,
                              void* d_out, int out_size)
{
    const float* x    = (const float*)d_in[0];   // [M, K]
    const float* wr   = (const float*)d_in[1];   // [N, K]
    // d_in[2] = weight_imag: algebraically dead
    const float* bias = (const float*)d_in[3];   // [N]
    float* out = (float*)d_out;

    void *p_xh, *p_wh;
    cudaGetSymbolAddress(&p_xh, g_xh);
    cudaGetSymbolAddress(&p_wh, g_wh);

    const int nthreads_prep = (int)((NX16 + NW16) / 256);
    to_fp16_fused<<<nthreads_prep, 256>>>(
        (const float4*)x, (uint4*)p_xh,
        (const float4*)wr, (uint4*)p_wh);

    cudaFuncSetAttribute(qgemm_fp16, cudaFuncAttributeMaxDynamicSharedMemorySize,
                         SMEM_TOTAL);

    const int nblocks = (M_DIM / BM) * (N_DIM / BN);   // 2048
    qgemm_fp16<<<nblocks, 256, SMEM_TOTAL>>>(
        (const __half*)p_xh, (const __half*)p_wh, bias, out);
}

// round 13
// speedup vs baseline: 1.0014x; 1.0014x over previous
#include <cuda_runtime.h>
#include <cuda_fp16.h>
#include <cstdint>

// QuantumLinear == x @ W_real^T + bias  (magnitude*cos(atan2(i,r)) == r identically;
// weight_imag is dead code).
//
// Round 11: fp16 m16n8k16 single pass with cross-barrier fragment pipeline (R10)
// + PAIRED tiles: one CP_WAIT(0)+__syncthreads per TWO k-tiles (64 barriers vs 128).
// 5 stages stay race-free: in-flight set at pair j = {2j,2j+1 computing, 2j+2 ready,
// 2j+3,2j+4 loading} = 5 distinct buffers. Prep kernel uses 16B stores.

#define M_DIM 8192
#define N_DIM 4096
#define K_DIM 4096

#define BM 128
#define BN 128
#define BK 32                       // fp16 elements per K-tile (64B rows)
#define STAGES 5
#define KTILES (K_DIM / BK)         // 128
#define KPAIRS (KTILES / 2)         // 64

// smem rows: 64B data + 16B pad = 80B stride -> conflict-free ldmatrix
#define ROW_STRIDE 80
#define TILE_BYTES (128 * ROW_STRIDE)          // 10240
#define STAGE_BYTES (2 * TILE_BYTES)           // 20480
#define SMEM_TOTAL (STAGES * STAGE_BYTES)      // 102400 (x2 CTAs = 200KB/SM)

// ---------------- scratch: fp16 copies ----------------
__device__ __half g_xh[(size_t)M_DIM * K_DIM];
__device__ __half g_wh[(size_t)N_DIM * K_DIM];

// ---------------- helpers ----------------
__device__ __forceinline__ uint32_t smem_u32(const void* p) {
    uint32_t a;
    asm("{ .reg .u64 t; cvta.to.shared.u64 t, %1; cvt.u32.u64 %0, t; }" : "=r"(a) : "l"(p));
    return a;
}

__device__ __forceinline__ void cp16(uint32_t dst, const void* src) {
    asm volatile("cp.async.cg.shared.global [%0], [%1], 16;" :: "r"(dst), "l"(src));
}
#define CP_COMMIT() asm volatile("cp.async.commit_group;" ::: "memory")
#define CP_WAIT(n)  asm volatile("cp.async.wait_group %0;" :: "n"(n) : "memory")

__device__ __forceinline__ void ldsm4(uint32_t* r, uint32_t addr) {
    asm volatile("ldmatrix.sync.aligned.m8n8.x4.shared.b16 {%0,%1,%2,%3}, [%4];"
                 : "=r"(r[0]), "=r"(r[1]), "=r"(r[2]), "=r"(r[3]) : "r"(addr));
}

__device__ __forceinline__ void mma16816(float* d, const uint32_t* a,
                                         uint32_t b0, uint32_t b1) {
    asm volatile(
        "mma.sync.aligned.m16n8k16.row.col.f32.f16.f16.f32 "
        "{%0,%1,%2,%3}, {%4,%5,%6,%7}, {%8,%9}, {%0,%1,%2,%3};"
        : "+f"(d[0]), "+f"(d[1]), "+f"(d[2]), "+f"(d[3])
        : "r"(a[0]), "r"(a[1]), "r"(a[2]), "r"(a[3]), "r"(b0), "r"(b1));
}

// ---------------- prep: fused fp32 -> fp16 (rn), 16B stores ----------------
// out 16B-units: X = M*K*2/16, W = N*K*2/16
#define NX16 ((size_t)M_DIM * K_DIM / 8)    // 4194304
#define NW16 ((size_t)N_DIM * K_DIM / 8)    // 2097152

__global__ __launch_bounds__(256)
void to_fp16_fused(const float4* __restrict__ xs, uint4* __restrict__ xd,
                   const float4* __restrict__ ws, uint4* __restrict__ wd)
{
    size_t i = (size_t)blockIdx.x * blockDim.x + threadIdx.x;
    const float4* s;
    uint4* d;
    if (i < NX16) { s = xs + 2 * i;            d = xd + i; }
    else          { size_t j = i - NX16; s = ws + 2 * j; d = wd + j; }
    float4 v0 = s[0];
    float4 v1 = s[1];
    __half2 h0 = __floats2half2_rn(v0.x, v0.y);
    __half2 h1 = __floats2half2_rn(v0.z, v0.w);
    __half2 h2 = __floats2half2_rn(v1.x, v1.y);
    __half2 h3 = __floats2half2_rn(v1.z, v1.w);
    uint4 o;
    o.x = *(uint32_t*)&h0;  o.y = *(uint32_t*)&h1;
    o.z = *(uint32_t*)&h2;  o.w = *(uint32_t*)&h3;
    *d = o;
}

// ---------------- GEMM ----------------
__global__ __launch_bounds__(256, 2)
void qgemm_fp16(const __half* __restrict__ X,   // [M, K] fp16
                const __half* __restrict__ W,   // [N, K] fp16
                const float* __restrict__ bias, // [N]
                float* __restrict__ out)        // [M, N]
{
    extern __shared__ char smem[];
    const uint32_t sb = smem_u32(smem);

    const int tid  = threadIdx.x;
    const int wid  = tid >> 5;
    const int lane = tid & 31;
    const int warpM = wid & 3;      // m offset 32*warpM
    const int warpN = wid >> 2;     // n offset 64*warpN

    // ---- grouped rasterization: 8 m-tiles per group column ----
    const int pid = blockIdx.x;
    const int group_id = pid >> 8;
    const int pid_m = (group_id << 3) + (pid & 7);
    const int pid_n = (pid & 255) >> 3;
    const int bm = pid_m * BM;
    const int bn = pid_n * BN;

    // ---- global load mapping: 2 rows per thread per tile, 16B chunks ----
    const int ldr   = tid >> 2;       // 0..63
    const int chunk = tid & 3;        // 0..3 (16B = 8 halves)
    const size_t aOff0 = (size_t)(bm + ldr) * K_DIM + chunk * 8;
    const size_t aOff1 = aOff0 + (size_t)64 * K_DIM;
    const size_t bOff0 = (size_t)(bn + ldr) * K_DIM + chunk * 8;
    const size_t bOff1 = bOff0 + (size_t)64 * K_DIM;
    const uint32_t sA0 = ldr * ROW_STRIDE + chunk * 16;
    const uint32_t sA1 = sA0 + 64 * ROW_STRIDE;

    // ---- ldmatrix lane bases ----
    const uint32_t aLane = sb +
        (uint32_t)((warpM * 32 + (lane & 15)) * ROW_STRIDE + ((lane >> 4) * 16));
    const uint32_t bLane = sb + TILE_BYTES +
        (uint32_t)((warpN * 64 + (lane & 7) + ((lane & 16) >> 1)) * ROW_STRIDE +
                   (((lane >> 3) & 1) * 16));

    float acc[2][8][4];
    #pragma unroll
    for (int i = 0; i < 2; i++)
        #pragma unroll
        for (int j = 0; j < 8; j++)
            #pragma unroll
            for (int q = 0; q < 4; q++)
                acc[i][j][q] = 0.0f;

    // ---- prologue: issue tiles 0..2 into stages 0..2 ----
    #pragma unroll
    for (int s = 0; s < 3; s++) {
        const int k0 = s * BK;
        const uint32_t st = sb + s * STAGE_BYTES;
        cp16(st + sA0, X + aOff0 + k0);
        cp16(st + sA1, X + aOff1 + k0);
        cp16(st + TILE_BYTES + sA0, W + bOff0 + k0);
        cp16(st + TILE_BYTES + sA1, W + bOff1 + k0);
    }
    CP_COMMIT();

    // fragment slots: A = even slice, B = odd slice of the rotation
    uint32_t arA[2][4], arB[2][4];
    uint32_t brA[4][4], brB[4][4];

    // preload tile0.slice0 into slot A
    CP_WAIT(0);
    __syncthreads();
    ldsm4(arA[0], aLane);
    ldsm4(arA[1], aLane + 16 * ROW_STRIDE);
    #pragma unroll
    for (int p = 0; p < 4; p++)
        ldsm4(brA[p], bLane + p * (16 * ROW_STRIDE));

    uint32_t b0 = 0;   // stage offset of tile 2j

    // ---- main loop: one wait+barrier per TWO tiles ----
    #pragma unroll 1
    for (int j = 0; j < KPAIRS; j++) {
        CP_WAIT(0);          // tiles up to 2j+2 arrived (issued >= 1 pair ago)
        __syncthreads();     // visible to all; buffers of pair j-1 free

        uint32_t b1 = b0 + STAGE_BYTES; if (b1 == SMEM_TOTAL) b1 = 0;
        uint32_t b2 = b1 + STAGE_BYTES; if (b2 == SMEM_TOTAL) b2 = 0;
        uint32_t b3 = b2 + STAGE_BYTES; if (b3 == SMEM_TOTAL) b3 = 0;
        uint32_t b4 = b3 + STAGE_BYTES; if (b4 == SMEM_TOTAL) b4 = 0;

        // issue loads for tiles 2j+3, 2j+4
        const int t3 = 2 * j + 3;
        if (t3 < KTILES) {
            const int k0 = t3 * BK;
            const uint32_t st = sb + b3;
            cp16(st + sA0, X + aOff0 + k0);
            cp16(st + sA1, X + aOff1 + k0);
            cp16(st + TILE_BYTES + sA0, W + bOff0 + k0);
            cp16(st + TILE_BYTES + sA1, W + bOff1 + k0);
        }
        const int t4 = 2 * j + 4;
        if (t4 < KTILES) {
            const int k0 = t4 * BK;
            const uint32_t st = sb + b4;
            cp16(st + sA0, X + aOff0 + k0);
            cp16(st + sA1, X + aOff1 + k0);
            cp16(st + TILE_BYTES + sA0, W + bOff0 + k0);
            cp16(st + TILE_BYTES + sA1, W + bOff1 + k0);
        }
        CP_COMMIT();

        // round 0: ldsm t0.s1 -> B ; mma t0.s0 from A
        ldsm4(arB[0], aLane + b0 + 32);
        ldsm4(arB[1], aLane + b0 + 32 + 16 * ROW_STRIDE);
        #pragma unroll
        for (int p = 0; p < 4; p++)
            ldsm4(brB[p], bLane + b0 + 32 + p * (16 * ROW_STRIDE));
        #pragma unroll
        for (int mt = 0; mt < 2; mt++)
            #pragma unroll
            for (int nt = 0; nt < 8; nt++)
                mma16816(acc[mt][nt], arA[mt],
                         brA[nt >> 1][(nt & 1) * 2], brA[nt >> 1][(nt & 1) * 2 + 1]);

        // round 1: ldsm t1.s0 -> A ; mma t0.s1 from B
        ldsm4(arA[0], aLane + b1);
        ldsm4(arA[1], aLane + b1 + 16 * ROW_STRIDE);
        #pragma unroll
        for (int p = 0; p < 4; p++)
            ldsm4(brA[p], bLane + b1 + p * (16 * ROW_STRIDE));
        #pragma unroll
        for (int mt = 0; mt < 2; mt++)
            #pragma unroll
            for (int nt = 0; nt < 8; nt++)
                mma16816(acc[mt][nt], arB[mt],
                         brB[nt >> 1][(nt & 1) * 2], brB[nt >> 1][(nt & 1) * 2 + 1]);

        // round 2: ldsm t1.s1 -> B ; mma t1.s0 from A
        ldsm4(arB[0], aLane + b1 + 32);
        ldsm4(arB[1], aLane + b1 + 32 + 16 * ROW_STRIDE);
        #pragma unroll
        for (int p = 0; p < 4; p++)
            ldsm4(brB[p], bLane + b1 + 32 + p * (16 * ROW_STRIDE));
        #pragma unroll
        for (int mt = 0; mt < 2; mt++)
            #pragma unroll
            for (int nt = 0; nt < 8; nt++)
                mma16816(acc[mt][nt], arA[mt],
                         brA[nt >> 1][(nt & 1) * 2], brA[nt >> 1][(nt & 1) * 2 + 1]);

        // round 3: ldsm t2.s0 -> A (cross-barrier preload) ; mma t1.s1 from B
        if (j + 1 < KPAIRS) {
            ldsm4(arA[0], aLane + b2);
            ldsm4(arA[1], aLane + b2 + 16 * ROW_STRIDE);
            #pragma unroll
            for (int p = 0; p < 4; p++)
                ldsm4(brA[p], bLane + b2 + p * (16 * ROW_STRIDE));
        }
        #pragma unroll
        for (int mt = 0; mt < 2; mt++)
            #pragma unroll
            for (int nt = 0; nt < 8; nt++)
                mma16816(acc[mt][nt], arB[mt],
                         brB[nt >> 1][(nt & 1) * 2], brB[nt >> 1][(nt & 1) * 2 + 1]);

        b0 = b2;
    }

    // ---- epilogue: direct stores + bias ----
    const int g = lane >> 2;
    const int t = lane & 3;
    #pragma unroll
    for (int mt = 0; mt < 2; mt++) {
        const int row0 = bm + warpM * 32 + mt * 16 + g;
        #pragma unroll
        for (int nt = 0; nt < 8; nt++) {
            const int col = bn + warpN * 64 + nt * 8 + 2 * t;
            const float2 b2v = *(const float2*)(bias + col);
            float2 o0, o1;
            o0.x = acc[mt][nt][0] + b2v.x;
            o0.y = acc[mt][nt][1] + b2v.y;
            o1.x = acc[mt][nt][2] + b2v.x;
            o1.y = acc[mt][nt][3] + b2v.y;
            *(float2*)(out + (size_t)row0 * N_DIM + col)       = o0;
            *(float2*)(out + (size_t)(row0 + 8) * N_DIM + col) = o1;
        }
    }
}

// ---------------- host ----------------
extern "C" void kernel_launch(void* const* d_in, const int* in_sizes, int n_in,
                              void* d_out, int out_size)
{
    const float* x    = (const float*)d_in[0];   // [M, K]
    const float* wr   = (const float*)d_in[1];   // [N, K]
    // d_in[2] = weight_imag: algebraically dead
    const float* bias = (const float*)d_in[3];   // [N]
    float* out = (float*)d_out;

    void *p_xh, *p_wh;
    cudaGetSymbolAddress(&p_xh, g_xh);
    cudaGetSymbolAddress(&p_wh, g_wh);

    const int nthreads_prep = (int)((NX16 + NW16) / 256);
    to_fp16_fused<<<nthreads_prep, 256>>>(
        (const float4*)x, (uint4*)p_xh,
        (const float4*)wr, (uint4*)p_wh);

    cudaFuncSetAttribute(qgemm_fp16, cudaFuncAttributeMaxDynamicSharedMemorySize,
                         SMEM_TOTAL);

    const int nblocks = (M_DIM / BM) * (N_DIM / BN);   // 2048
    qgemm_fp16<<<nblocks, 256, SMEM_TOTAL>>>(
        (const __half*)p_xh, (const __half*)p_wh, bias, out);
}

// round 14
// speedup vs baseline: 1.0023x; 1.0009x over previous
#include <cuda_runtime.h>
#include <cuda_fp16.h>
#include <cstdint>

// QuantumLinear == x @ W_real^T + bias  (magnitude*cos(atan2(i,r)) == r identically;
// weight_imag is dead code).
//
// Round 11: fp16 m16n8k16 single pass with cross-barrier fragment pipeline (R10)
// + PAIRED tiles: one CP_WAIT(0)+__syncthreads per TWO k-tiles (64 barriers vs 128).
// 5 stages stay race-free: in-flight set at pair j = {2j,2j+1 computing, 2j+2 ready,
// 2j+3,2j+4 loading} = 5 distinct buffers. Prep kernel uses 16B stores.

#define M_DIM 8192
#define N_DIM 4096
#define K_DIM 4096

#define BM 128
#define BN 128
#define BK 32                       // fp16 elements per K-tile (64B rows)
#define STAGES 5
#define KTILES (K_DIM / BK)         // 128
#define KPAIRS (KTILES / 2)         // 64

// smem rows: 64B data + 16B pad = 80B stride -> conflict-free ldmatrix
#define ROW_STRIDE 80
#define TILE_BYTES (128 * ROW_STRIDE)          // 10240
#define STAGE_BYTES (2 * TILE_BYTES)           // 20480
#define SMEM_TOTAL (STAGES * STAGE_BYTES)      // 102400 (x2 CTAs = 200KB/SM)

// ---------------- scratch: fp16 copies ----------------
__device__ __half g_xh[(size_t)M_DIM * K_DIM];
__device__ __half g_wh[(size_t)N_DIM * K_DIM];

// ---------------- helpers ----------------
__device__ __forceinline__ uint32_t smem_u32(const void* p) {
    uint32_t a;
    asm("{ .reg .u64 t; cvta.to.shared.u64 t, %1; cvt.u32.u64 %0, t; }" : "=r"(a) : "l"(p));
    return a;
}

__device__ __forceinline__ void cp16(uint32_t dst, const void* src) {
    asm volatile("cp.async.cg.shared.global [%0], [%1], 16;" :: "r"(dst), "l"(src));
}
#define CP_COMMIT() asm volatile("cp.async.commit_group;" ::: "memory")
#define CP_WAIT(n)  asm volatile("cp.async.wait_group %0;" :: "n"(n) : "memory")

__device__ __forceinline__ void ldsm4(uint32_t* r, uint32_t addr) {
    asm volatile("ldmatrix.sync.aligned.m8n8.x4.shared.b16 {%0,%1,%2,%3}, [%4];"
                 : "=r"(r[0]), "=r"(r[1]), "=r"(r[2]), "=r"(r[3]) : "r"(addr));
}

__device__ __forceinline__ void mma16816(float* d, const uint32_t* a,
                                         uint32_t b0, uint32_t b1) {
    asm volatile(
        "mma.sync.aligned.m16n8k16.row.col.f32.f16.f16.f32 "
        "{%0,%1,%2,%3}, {%4,%5,%6,%7}, {%8,%9}, {%0,%1,%2,%3};"
        : "+f"(d[0]), "+f"(d[1]), "+f"(d[2]), "+f"(d[3])
        : "r"(a[0]), "r"(a[1]), "r"(a[2]), "r"(a[3]), "r"(b0), "r"(b1));
}

// ---------------- prep: fused fp32 -> fp16 (rn), 16B stores ----------------
// out 16B-units: X = M*K*2/16, W = N*K*2/16
#define NX16 ((size_t)M_DIM * K_DIM / 8)    // 4194304
#define NW16 ((size_t)N_DIM * K_DIM / 8)    // 2097152

__global__ __launch_bounds__(256)
void to_fp16_fused(const float4* __restrict__ xs, uint4* __restrict__ xd,
                   const float4* __restrict__ ws, uint4* __restrict__ wd)
{
    size_t i = (size_t)blockIdx.x * blockDim.x + threadIdx.x;
    const float4* s;
    uint4* d;
    if (i < NX16) { s = xs + 2 * i;            d = xd + i; }
    else          { size_t j = i - NX16; s = ws + 2 * j; d = wd + j; }
    float4 v0 = s[0];
    float4 v1 = s[1];
    __half2 h0 = __floats2half2_rn(v0.x, v0.y);
    __half2 h1 = __floats2half2_rn(v0.z, v0.w);
    __half2 h2 = __floats2half2_rn(v1.x, v1.y);
    __half2 h3 = __floats2half2_rn(v1.z, v1.w);
    uint4 o;
    o.x = *(uint32_t*)&h0;  o.y = *(uint32_t*)&h1;
    o.z = *(uint32_t*)&h2;  o.w = *(uint32_t*)&h3;
    *d = o;
}

// ---------------- GEMM ----------------
__global__ __launch_bounds__(256, 2)
void qgemm_fp16(const __half* __restrict__ X,   // [M, K] fp16
                const __half* __restrict__ W,   // [N, K] fp16
                const float* __restrict__ bias, // [N]
                float* __restrict__ out)        // [M, N]
{
    extern __shared__ char smem[];
    const uint32_t sb = smem_u32(smem);

    const int tid  = threadIdx.x;
    const int wid  = tid >> 5;
    const int lane = tid & 31;
    const int warpM = wid & 3;      // m offset 32*warpM
    const int warpN = wid >> 2;     // n offset 64*warpN

    // ---- grouped rasterization: 8 m-tiles per group column ----
    const int pid = blockIdx.x;
    const int group_id = pid >> 8;
    const int pid_m = (group_id << 3) + (pid & 7);
    const int pid_n = (pid & 255) >> 3;
    const int bm = pid_m * BM;
    const int bn = pid_n * BN;

    // ---- global load mapping: 2 rows per thread per tile, 16B chunks ----
    const int ldr   = tid >> 2;       // 0..63
    const int chunk = tid & 3;        // 0..3 (16B = 8 halves)
    const size_t aOff0 = (size_t)(bm + ldr) * K_DIM + chunk * 8;
    const size_t aOff1 = aOff0 + (size_t)64 * K_DIM;
    const size_t bOff0 = (size_t)(bn + ldr) * K_DIM + chunk * 8;
    const size_t bOff1 = bOff0 + (size_t)64 * K_DIM;
    const uint32_t sA0 = ldr * ROW_STRIDE + chunk * 16;
    const uint32_t sA1 = sA0 + 64 * ROW_STRIDE;

    // ---- ldmatrix lane bases ----
    const uint32_t aLane = sb +
        (uint32_t)((warpM * 32 + (lane & 15)) * ROW_STRIDE + ((lane >> 4) * 16));
    const uint32_t bLane = sb + TILE_BYTES +
        (uint32_t)((warpN * 64 + (lane & 7) + ((lane & 16) >> 1)) * ROW_STRIDE +
                   (((lane >> 3) & 1) * 16));

    float acc[2][8][4];
    #pragma unroll
    for (int i = 0; i < 2; i++)
        #pragma unroll
        for (int j = 0; j < 8; j++)
            #pragma unroll
            for (int q = 0; q < 4; q++)
                acc[i][j][q] = 0.0f;

    // ---- prologue: issue tiles 0..2 into stages 0..2 ----
    #pragma unroll
    for (int s = 0; s < 3; s++) {
        const int k0 = s * BK;
        const uint32_t st = sb + s * STAGE_BYTES;
        cp16(st + sA0, X + aOff0 + k0);
        cp16(st + sA1, X + aOff1 + k0);
        cp16(st + TILE_BYTES + sA0, W + bOff0 + k0);
        cp16(st + TILE_BYTES + sA1, W + bOff1 + k0);
    }
    CP_COMMIT();

    // fragment slots: A = even slice, B = odd slice of the rotation
    uint32_t arA[2][4], arB[2][4];
    uint32_t brA[4][4], brB[4][4];

    // preload tile0.slice0 into slot A
    CP_WAIT(0);
    __syncthreads();
    ldsm4(arA[0], aLane);
    ldsm4(arA[1], aLane + 16 * ROW_STRIDE);
    #pragma unroll
    for (int p = 0; p < 4; p++)
        ldsm4(brA[p], bLane + p * (16 * ROW_STRIDE));

    uint32_t b0 = 0;   // stage offset of tile 2j

    // ---- main loop: one wait+barrier per TWO tiles ----
    #pragma unroll 1
    for (int j = 0; j < KPAIRS; j++) {
        CP_WAIT(0);          // tiles up to 2j+2 arrived (issued >= 1 pair ago)
        __syncthreads();     // visible to all; buffers of pair j-1 free

        uint32_t b1 = b0 + STAGE_BYTES; if (b1 == SMEM_TOTAL) b1 = 0;
        uint32_t b2 = b1 + STAGE_BYTES; if (b2 == SMEM_TOTAL) b2 = 0;
        uint32_t b3 = b2 + STAGE_BYTES; if (b3 == SMEM_TOTAL) b3 = 0;
        uint32_t b4 = b3 + STAGE_BYTES; if (b4 == SMEM_TOTAL) b4 = 0;

        // issue loads for tiles 2j+3, 2j+4
        const int t3 = 2 * j + 3;
        if (t3 < KTILES) {
            const int k0 = t3 * BK;
            const uint32_t st = sb + b3;
            cp16(st + sA0, X + aOff0 + k0);
            cp16(st + sA1, X + aOff1 + k0);
            cp16(st + TILE_BYTES + sA0, W + bOff0 + k0);
            cp16(st + TILE_BYTES + sA1, W + bOff1 + k0);
        }
        const int t4 = 2 * j + 4;
        if (t4 < KTILES) {
            const int k0 = t4 * BK;
            const uint32_t st = sb + b4;
            cp16(st + sA0, X + aOff0 + k0);
            cp16(st + sA1, X + aOff1 + k0);
            cp16(st + TILE_BYTES + sA0, W + bOff0 + k0);
            cp16(st + TILE_BYTES + sA1, W + bOff1 + k0);
        }
        CP_COMMIT();

        // round 0: ldsm t0.s1 -> B ; mma t0.s0 from A
        ldsm4(arB[0], aLane + b0 + 32);
        ldsm4(arB[1], aLane + b0 + 32 + 16 * ROW_STRIDE);
        #pragma unroll
        for (int p = 0; p < 4; p++)
            ldsm4(brB[p], bLane + b0 + 32 + p * (16 * ROW_STRIDE));
        #pragma unroll
        for (int mt = 0; mt < 2; mt++)
            #pragma unroll
            for (int nt = 0; nt < 8; nt++)
                mma16816(acc[mt][nt], arA[mt],
                         brA[nt >> 1][(nt & 1) * 2], brA[nt >> 1][(nt & 1) * 2 + 1]);

        // round 1: ldsm t1.s0 -> A ; mma t0.s1 from B
        ldsm4(arA[0], aLane + b1);
        ldsm4(arA[1], aLane + b1 + 16 * ROW_STRIDE);
        #pragma unroll
        for (int p = 0; p < 4; p++)
            ldsm4(brA[p], bLane + b1 + p * (16 * ROW_STRIDE));
        #pragma unroll
        for (int mt = 0; mt < 2; mt++)
            #pragma unroll
            for (int nt = 0; nt < 8; nt++)
                mma16816(acc[mt][nt], arB[mt],
                         brB[nt >> 1][(nt & 1) * 2], brB[nt >> 1][(nt & 1) * 2 + 1]);

        // round 2: ldsm t1.s1 -> B ; mma t1.s0 from A
        ldsm4(arB[0], aLane + b1 + 32);
        ldsm4(arB[1], aLane + b1 + 32 + 16 * ROW_STRIDE);
        #pragma unroll
        for (int p = 0; p < 4; p++)
            ldsm4(brB[p], bLane + b1 + 32 + p * (16 * ROW_STRIDE));
        #pragma unroll
        for (int mt = 0; mt < 2; mt++)
            #pragma unroll
            for (int nt = 0; nt < 8; nt++)
                mma16816(acc[mt][nt], arA[mt],
                         brA[nt >> 1][(nt & 1) * 2], brA[nt >> 1][(nt & 1) * 2 + 1]);

        // round 3: ldsm t2.s0 -> A (cross-barrier preload) ; mma t1.s1 from B
        if (j + 1 < KPAIRS) {
            ldsm4(arA[0], aLane + b2);
            ldsm4(arA[1], aLane + b2 + 16 * ROW_STRIDE);
            #pragma unroll
            for (int p = 0; p < 4; p++)
                ldsm4(brA[p], bLane + b2 + p * (16 * ROW_STRIDE));
        }
        #pragma unroll
        for (int mt = 0; mt < 2; mt++)
            #pragma unroll
            for (int nt = 0; nt < 8; nt++)
                mma16816(acc[mt][nt], arB[mt],
                         brB[nt >> 1][(nt & 1) * 2], brB[nt >> 1][(nt & 1) * 2 + 1]);

        b0 = b2;
    }

    // ---- epilogue: direct stores + bias ----
    const int g = lane >> 2;
    const int t = lane & 3;
    #pragma unroll
    for (int mt = 0; mt < 2; mt++) {
        const int row0 = bm + warpM * 32 + mt * 16 + g;
        #pragma unroll
        for (int nt = 0; nt < 8; nt++) {
            const int col = bn + warpN * 64 + nt * 8 + 2 * t;
            const float2 b2v = *(const float2*)(bias + col);
            float2 o0, o1;
            o0.x = acc[mt][nt][0] + b2v.x;
            o0.y = acc[mt][nt][1] + b2v.y;
            o1.x = acc[mt][nt][2] + b2v.x;
            o1.y = acc[mt][nt][3] + b2v.y;
            *(float2*)(out + (size_t)row0 * N_DIM + col)       = o0;
            *(float2*)(out + (size_t)(row0 + 8) * N_DIM + col) = o1;
        }
    }
}

// ---------------- host ----------------
extern "C" void kernel_launch(void* const* d_in, const int* in_sizes, int n_in,
                              void* d_out, int out_size)
{
    const float* x    = (const float*)d_in[0];   // [M, K]
    const float* wr   = (const float*)d_in[1];   // [N, K]
    // d_in[2] = weight_imag: algebraically dead
    const float* bias = (const float*)d_in[3];   // [N]
    float* out = (float*)d_out;

    void *p_xh, *p_wh;
    cudaGetSymbolAddress(&p_xh, g_xh);
    cudaGetSymbolAddress(&p_wh, g_wh);

    const int nthreads_prep = (int)((NX16 + NW16) / 256);
    to_fp16_fused<<<nthreads_prep, 256>>>(
        (const float4*)x, (uint4*)p_xh,
        (const float4*)wr, (uint4*)p_wh);

    cudaFuncSetAttribute(qgemm_fp16, cudaFuncAttributeMaxDynamicSharedMemorySize,
                         SMEM_TOTAL);

    const int nblocks = (M_DIM / BM) * (N_DIM / BN);   // 2048
    qgemm_fp16<<<nblocks, 256, SMEM_TOTAL>>>(
        (const __half*)p_xh, (const __half*)p_wh, bias, out);
}

// round 15
// speedup vs baseline: 1.0751x; 1.0726x over previous
#include <cuda_runtime.h>
#include <cuda_fp16.h>
#include <cstdint>

// QuantumLinear == x @ W_real^T + bias  (magnitude*cos(atan2(i,r)) == r identically;
// weight_imag is dead code).
//
// Round 15: revert GEMM to the best-measured R10 schedule (697us GEMM, tensor 65%):
// fp16 m16n8k16 single pass, 5-stage cp.async with CP_WAIT(2) (2 groups in flight),
// cross-barrier ldmatrix fragment pipeline. Keep R14's 16B-store prep (~38us).
// Tested-and-rejected: paired barriers w/ wait(0) (R14, +51us), BK=64/3-stage (R8,
// +214us), 64x64 warp tile / 1 CTA (R6), 3-pass bf16 (R3), tf32 (R4/R5).

#define M_DIM 8192
#define N_DIM 4096
#define K_DIM 4096

#define BM 128
#define BN 128
#define BK 32                       // fp16 elements per K-tile (64B rows)
#define STAGES 5
#define KTILES (K_DIM / BK)         // 128

// smem rows: 64B data + 16B pad = 80B stride -> conflict-free ldmatrix
#define ROW_STRIDE 80
#define TILE_BYTES (128 * ROW_STRIDE)          // 10240
#define STAGE_BYTES (2 * TILE_BYTES)           // 20480
#define SMEM_TOTAL (STAGES * STAGE_BYTES)      // 102400 (x2 CTAs = 200KB/SM)

// ---------------- scratch: fp16 copies ----------------
__device__ __half g_xh[(size_t)M_DIM * K_DIM];
__device__ __half g_wh[(size_t)N_DIM * K_DIM];

// ---------------- helpers ----------------
__device__ __forceinline__ uint32_t smem_u32(const void* p) {
    uint32_t a;
    asm("{ .reg .u64 t; cvta.to.shared.u64 t, %1; cvt.u32.u64 %0, t; }" : "=r"(a) : "l"(p));
    return a;
}

__device__ __forceinline__ void cp16(uint32_t dst, const void* src) {
    asm volatile("cp.async.cg.shared.global [%0], [%1], 16;" :: "r"(dst), "l"(src));
}
#define CP_COMMIT() asm volatile("cp.async.commit_group;" ::: "memory")
#define CP_WAIT(n)  asm volatile("cp.async.wait_group %0;" :: "n"(n) : "memory")

__device__ __forceinline__ void ldsm4(uint32_t* r, uint32_t addr) {
    asm volatile("ldmatrix.sync.aligned.m8n8.x4.shared.b16 {%0,%1,%2,%3}, [%4];"
                 : "=r"(r[0]), "=r"(r[1]), "=r"(r[2]), "=r"(r[3]) : "r"(addr));
}

__device__ __forceinline__ void mma16816(float* d, const uint32_t* a,
                                         uint32_t b0, uint32_t b1) {
    asm volatile(
        "mma.sync.aligned.m16n8k16.row.col.f32.f16.f16.f32 "
        "{%0,%1,%2,%3}, {%4,%5,%6,%7}, {%8,%9}, {%0,%1,%2,%3};"
        : "+f"(d[0]), "+f"(d[1]), "+f"(d[2]), "+f"(d[3])
        : "r"(a[0]), "r"(a[1]), "r"(a[2]), "r"(a[3]), "r"(b0), "r"(b1));
}

// ---------------- prep: fused fp32 -> fp16 (rn), 16B stores ----------------
#define NX16 ((size_t)M_DIM * K_DIM / 8)    // 4194304 16B-output units for X
#define NW16 ((size_t)N_DIM * K_DIM / 8)    // 2097152 for W

__global__ __launch_bounds__(256)
void to_fp16_fused(const float4* __restrict__ xs, uint4* __restrict__ xd,
                   const float4* __restrict__ ws, uint4* __restrict__ wd)
{
    size_t i = (size_t)blockIdx.x * blockDim.x + threadIdx.x;
    const float4* s;
    uint4* d;
    if (i < NX16) { s = xs + 2 * i;            d = xd + i; }
    else          { size_t j = i - NX16; s = ws + 2 * j; d = wd + j; }
    float4 v0 = s[0];
    float4 v1 = s[1];
    __half2 h0 = __floats2half2_rn(v0.x, v0.y);
    __half2 h1 = __floats2half2_rn(v0.z, v0.w);
    __half2 h2 = __floats2half2_rn(v1.x, v1.y);
    __half2 h3 = __floats2half2_rn(v1.z, v1.w);
    uint4 o;
    o.x = *(uint32_t*)&h0;  o.y = *(uint32_t*)&h1;
    o.z = *(uint32_t*)&h2;  o.w = *(uint32_t*)&h3;
    *d = o;
}

// ---------------- GEMM (identical to Round 10 best) ----------------
__global__ __launch_bounds__(256, 2)
void qgemm_fp16(const __half* __restrict__ X,   // [M, K] fp16
                const __half* __restrict__ W,   // [N, K] fp16
                const float* __restrict__ bias, // [N]
                float* __restrict__ out)        // [M, N]
{
    extern __shared__ char smem[];
    const uint32_t sb = smem_u32(smem);

    const int tid  = threadIdx.x;
    const int wid  = tid >> 5;
    const int lane = tid & 31;
    const int warpM = wid & 3;      // m offset 32*warpM
    const int warpN = wid >> 2;     // n offset 64*warpN

    // ---- grouped rasterization: 8 m-tiles per group column ----
    const int pid = blockIdx.x;
    const int group_id = pid >> 8;
    const int pid_m = (group_id << 3) + (pid & 7);
    const int pid_n = (pid & 255) >> 3;
    const int bm = pid_m * BM;
    const int bn = pid_n * BN;

    // ---- global load mapping: 2 rows per thread per tile, 16B chunks ----
    const int ldr   = tid >> 2;       // 0..63
    const int chunk = tid & 3;        // 0..3 (16B = 8 halves)
    const size_t aOff0 = (size_t)(bm + ldr) * K_DIM + chunk * 8;
    const size_t aOff1 = aOff0 + (size_t)64 * K_DIM;
    const size_t bOff0 = (size_t)(bn + ldr) * K_DIM + chunk * 8;
    const size_t bOff1 = bOff0 + (size_t)64 * K_DIM;
    const uint32_t sA0 = ldr * ROW_STRIDE + chunk * 16;
    const uint32_t sA1 = sA0 + 64 * ROW_STRIDE;

    // ---- ldmatrix lane bases ----
    const uint32_t aLane = sb +
        (uint32_t)((warpM * 32 + (lane & 15)) * ROW_STRIDE + ((lane >> 4) * 16));
    const uint32_t bLane = sb + TILE_BYTES +
        (uint32_t)((warpN * 64 + (lane & 7) + ((lane & 16) >> 1)) * ROW_STRIDE +
                   (((lane >> 3) & 1) * 16));

    float acc[2][8][4];
    #pragma unroll
    for (int i = 0; i < 2; i++)
        #pragma unroll
        for (int j = 0; j < 8; j++)
            #pragma unroll
            for (int q = 0; q < 4; q++)
                acc[i][j][q] = 0.0f;

    // ---- prologue: issue stages 0..STAGES-2 (4 groups) ----
    #pragma unroll
    for (int s = 0; s < STAGES - 1; s++) {
        const int k0 = s * BK;
        const uint32_t st = sb + s * STAGE_BYTES;
        cp16(st + sA0, X + aOff0 + k0);
        cp16(st + sA1, X + aOff1 + k0);
        cp16(st + TILE_BYTES + sA0, W + bOff0 + k0);
        cp16(st + TILE_BYTES + sA1, W + bOff1 + k0);
        CP_COMMIT();
    }

    uint32_t bufC = 0;
    uint32_t bufL = (STAGES - 1) * STAGE_BYTES;

    // fragment buffers: [0]=slice0, [1]=slice1 (fixed roles)
    uint32_t ar[2][2][4];   // [slice][mt][reg]
    uint32_t br[2][4][4];   // [slice][npair][reg]

    // ---- preload slice0 fragments of stage 0 ----
    CP_WAIT(3);            // stage 0 arrived (own thread)
    __syncthreads();       // visible to all
    ldsm4(ar[0][0], aLane + bufC);
    ldsm4(ar[0][1], aLane + bufC + 16 * ROW_STRIDE);
    #pragma unroll
    for (int p = 0; p < 4; p++)
        ldsm4(br[0][p], bLane + bufC + p * (16 * ROW_STRIDE));

    // ---- main loop (cross-barrier fragment pipeline) ----
    #pragma unroll 1
    for (int s = 0; s < KTILES; s++) {
        // groups committed so far: 4 + s; all but 2 done -> stages 0..s+1 ready
        CP_WAIT(2);
        __syncthreads();   // stage s+1 now globally visible; buffer (s-1)%5 free

        // issue cp for stage s+4 into buffer (s-1)%5
        const int ls = s + STAGES - 1;
        if (ls < KTILES) {
            const int k0 = ls * BK;
            const uint32_t st = sb + bufL;
            cp16(st + sA0, X + aOff0 + k0);
            cp16(st + sA1, X + aOff1 + k0);
            cp16(st + TILE_BYTES + sA0, W + bOff0 + k0);
            cp16(st + TILE_BYTES + sA1, W + bOff1 + k0);
        }
        CP_COMMIT();

        // prefetch slice1 of stage s
        {
            const uint32_t o = bufC + 32;
            ldsm4(ar[1][0], aLane + o);
            ldsm4(ar[1][1], aLane + o + 16 * ROW_STRIDE);
            #pragma unroll
            for (int p = 0; p < 4; p++)
                ldsm4(br[1][p], bLane + o + p * (16 * ROW_STRIDE));
        }

        // mma slice0 (fragments preloaded last iteration)
        #pragma unroll
        for (int mt = 0; mt < 2; mt++)
            #pragma unroll
            for (int nt = 0; nt < 8; nt++)
                mma16816(acc[mt][nt], ar[0][mt],
                         br[0][nt >> 1][(nt & 1) * 2],
                         br[0][nt >> 1][(nt & 1) * 2 + 1]);

        // prefetch slice0 of stage s+1 (data visible since this iter's barrier;
        // its buffer is not rewritten until iter s+2 -> safe)
        uint32_t bufN = bufC + STAGE_BYTES;
        if (bufN == SMEM_TOTAL) bufN = 0;
        if (s + 1 < KTILES) {
            ldsm4(ar[0][0], aLane + bufN);
            ldsm4(ar[0][1], aLane + bufN + 16 * ROW_STRIDE);
            #pragma unroll
            for (int p = 0; p < 4; p++)
                ldsm4(br[0][p], bLane + bufN + p * (16 * ROW_STRIDE));
        }

        // mma slice1
        #pragma unroll
        for (int mt = 0; mt < 2; mt++)
            #pragma unroll
            for (int nt = 0; nt < 8; nt++)
                mma16816(acc[mt][nt], ar[1][mt],
                         br[1][nt >> 1][(nt & 1) * 2],
                         br[1][nt >> 1][(nt & 1) * 2 + 1]);

        bufC = bufN;
        bufL += STAGE_BYTES; if (bufL == SMEM_TOTAL) bufL = 0;
    }

    // ---- epilogue: direct stores + bias ----
    const int g = lane >> 2;
    const int t = lane & 3;
    #pragma unroll
    for (int mt = 0; mt < 2; mt++) {
        const int row0 = bm + warpM * 32 + mt * 16 + g;
        #pragma unroll
        for (int nt = 0; nt < 8; nt++) {
            const int col = bn + warpN * 64 + nt * 8 + 2 * t;
            const float2 b2 = *(const float2*)(bias + col);
            float2 o0, o1;
            o0.x = acc[mt][nt][0] + b2.x;
            o0.y = acc[mt][nt][1] + b2.y;
            o1.x = acc[mt][nt][2] + b2.x;
            o1.y = acc[mt][nt][3] + b2.y;
            *(float2*)(out + (size_t)row0 * N_DIM + col)       = o0;
            *(float2*)(out + (size_t)(row0 + 8) * N_DIM + col) = o1;
        }
    }
}

// ---------------- host ----------------
extern "C" void kernel_launch(void* const* d_in, const int* in_sizes, int n_in,
                              void* d_out, int out_size)
{
    const float* x    = (const float*)d_in[0];   // [M, K]
    const float* wr   = (const float*)d_in[1];   // [N, K]
    // d_in[2] = weight_imag: algebraically dead
    const float* bias = (const float*)d_in[3];   // [N]
    float* out = (float*)d_out;

    void *p_xh, *p_wh;
    cudaGetSymbolAddress(&p_xh, g_xh);
    cudaGetSymbolAddress(&p_wh, g_wh);

    const int nblocks_prep = (int)((NX16 + NW16) / 256);
    to_fp16_fused<<<nblocks_prep, 256>>>(
        (const float4*)x, (uint4*)p_xh,
        (const float4*)wr, (uint4*)p_wh);

    cudaFuncSetAttribute(qgemm_fp16, cudaFuncAttributeMaxDynamicSharedMemorySize,
                         SMEM_TOTAL);

    const int nblocks = (M_DIM / BM) * (N_DIM / BN);   // 2048
    qgemm_fp16<<<nblocks, 256, SMEM_TOTAL>>>(
        (const __half*)p_xh, (const __half*)p_wh, bias, out);
}

// round 16
// speedup vs baseline: 1.0775x; 1.0022x over previous
#include <cuda_runtime.h>
#include <cuda_fp16.h>
#include <cstdint>

// QuantumLinear == x @ W_real^T + bias  (magnitude*cos(atan2(i,r)) == r identically;
// weight_imag is dead code).
//
// Round 16: R15 schedule (fp16 m16n8k16 single pass, 5-stage cp.async CP_WAIT(2),
// cross-barrier fragment pipeline) with the post-barrier tile body REORDERED:
// latency-critical ldsm first, bulk cp.async issue moved behind mma slice0
// (its data isn't needed for ~2 tile bodies). Same commit-per-iteration count.

#define M_DIM 8192
#define N_DIM 4096
#define K_DIM 4096

#define BM 128
#define BN 128
#define BK 32                       // fp16 elements per K-tile (64B rows)
#define STAGES 5
#define KTILES (K_DIM / BK)         // 128

// smem rows: 64B data + 16B pad = 80B stride -> conflict-free ldmatrix
#define ROW_STRIDE 80
#define TILE_BYTES (128 * ROW_STRIDE)          // 10240
#define STAGE_BYTES (2 * TILE_BYTES)           // 20480
#define SMEM_TOTAL (STAGES * STAGE_BYTES)      // 102400 (x2 CTAs = 200KB/SM)

// ---------------- scratch: fp16 copies ----------------
__device__ __half g_xh[(size_t)M_DIM * K_DIM];
__device__ __half g_wh[(size_t)N_DIM * K_DIM];

// ---------------- helpers ----------------
__device__ __forceinline__ uint32_t smem_u32(const void* p) {
    uint32_t a;
    asm("{ .reg .u64 t; cvta.to.shared.u64 t, %1; cvt.u32.u64 %0, t; }" : "=r"(a) : "l"(p));
    return a;
}

__device__ __forceinline__ void cp16(uint32_t dst, const void* src) {
    asm volatile("cp.async.cg.shared.global [%0], [%1], 16;" :: "r"(dst), "l"(src));
}
#define CP_COMMIT() asm volatile("cp.async.commit_group;" ::: "memory")
#define CP_WAIT(n)  asm volatile("cp.async.wait_group %0;" :: "n"(n) : "memory")

__device__ __forceinline__ void ldsm4(uint32_t* r, uint32_t addr) {
    asm volatile("ldmatrix.sync.aligned.m8n8.x4.shared.b16 {%0,%1,%2,%3}, [%4];"
                 : "=r"(r[0]), "=r"(r[1]), "=r"(r[2]), "=r"(r[3]) : "r"(addr));
}

__device__ __forceinline__ void mma16816(float* d, const uint32_t* a,
                                         uint32_t b0, uint32_t b1) {
    asm volatile(
        "mma.sync.aligned.m16n8k16.row.col.f32.f16.f16.f32 "
        "{%0,%1,%2,%3}, {%4,%5,%6,%7}, {%8,%9}, {%0,%1,%2,%3};"
        : "+f"(d[0]), "+f"(d[1]), "+f"(d[2]), "+f"(d[3])
        : "r"(a[0]), "r"(a[1]), "r"(a[2]), "r"(a[3]), "r"(b0), "r"(b1));
}

// ---------------- prep: fused fp32 -> fp16 (rn), 16B stores ----------------
#define NX16 ((size_t)M_DIM * K_DIM / 8)    // 4194304 16B-output units for X
#define NW16 ((size_t)N_DIM * K_DIM / 8)    // 2097152 for W

__global__ __launch_bounds__(256)
void to_fp16_fused(const float4* __restrict__ xs, uint4* __restrict__ xd,
                   const float4* __restrict__ ws, uint4* __restrict__ wd)
{
    size_t i = (size_t)blockIdx.x * blockDim.x + threadIdx.x;
    const float4* s;
    uint4* d;
    if (i < NX16) { s = xs + 2 * i;            d = xd + i; }
    else          { size_t j = i - NX16; s = ws + 2 * j; d = wd + j; }
    float4 v0 = s[0];
    float4 v1 = s[1];
    __half2 h0 = __floats2half2_rn(v0.x, v0.y);
    __half2 h1 = __floats2half2_rn(v0.z, v0.w);
    __half2 h2 = __floats2half2_rn(v1.x, v1.y);
    __half2 h3 = __floats2half2_rn(v1.z, v1.w);
    uint4 o;
    o.x = *(uint32_t*)&h0;  o.y = *(uint32_t*)&h1;
    o.z = *(uint32_t*)&h2;  o.w = *(uint32_t*)&h3;
    *d = o;
}

// ---------------- GEMM ----------------
__global__ __launch_bounds__(256, 2)
void qgemm_fp16(const __half* __restrict__ X,   // [M, K] fp16
                const __half* __restrict__ W,   // [N, K] fp16
                const float* __restrict__ bias, // [N]
                float* __restrict__ out)        // [M, N]
{
    extern __shared__ char smem[];
    const uint32_t sb = smem_u32(smem);

    const int tid  = threadIdx.x;
    const int wid  = tid >> 5;
    const int lane = tid & 31;
    const int warpM = wid & 3;      // m offset 32*warpM
    const int warpN = wid >> 2;     // n offset 64*warpN

    // ---- grouped rasterization: 8 m-tiles per group column ----
    const int pid = blockIdx.x;
    const int group_id = pid >> 8;
    const int pid_m = (group_id << 3) + (pid & 7);
    const int pid_n = (pid & 255) >> 3;
    const int bm = pid_m * BM;
    const int bn = pid_n * BN;

    // ---- global load mapping: 2 rows per thread per tile, 16B chunks ----
    const int ldr   = tid >> 2;       // 0..63
    const int chunk = tid & 3;        // 0..3 (16B = 8 halves)
    const size_t aOff0 = (size_t)(bm + ldr) * K_DIM + chunk * 8;
    const size_t aOff1 = aOff0 + (size_t)64 * K_DIM;
    const size_t bOff0 = (size_t)(bn + ldr) * K_DIM + chunk * 8;
    const size_t bOff1 = bOff0 + (size_t)64 * K_DIM;
    const uint32_t sA0 = ldr * ROW_STRIDE + chunk * 16;
    const uint32_t sA1 = sA0 + 64 * ROW_STRIDE;

    // ---- ldmatrix lane bases ----
    const uint32_t aLane = sb +
        (uint32_t)((warpM * 32 + (lane & 15)) * ROW_STRIDE + ((lane >> 4) * 16));
    const uint32_t bLane = sb + TILE_BYTES +
        (uint32_t)((warpN * 64 + (lane & 7) + ((lane & 16) >> 1)) * ROW_STRIDE +
                   (((lane >> 3) & 1) * 16));

    float acc[2][8][4];
    #pragma unroll
    for (int i = 0; i < 2; i++)
        #pragma unroll
        for (int j = 0; j < 8; j++)
            #pragma unroll
            for (int q = 0; q < 4; q++)
                acc[i][j][q] = 0.0f;

    // ---- prologue: issue stages 0..STAGES-2 (4 groups) ----
    #pragma unroll
    for (int s = 0; s < STAGES - 1; s++) {
        const int k0 = s * BK;
        const uint32_t st = sb + s * STAGE_BYTES;
        cp16(st + sA0, X + aOff0 + k0);
        cp16(st + sA1, X + aOff1 + k0);
        cp16(st + TILE_BYTES + sA0, W + bOff0 + k0);
        cp16(st + TILE_BYTES + sA1, W + bOff1 + k0);
        CP_COMMIT();
    }

    uint32_t bufC = 0;
    uint32_t bufL = (STAGES - 1) * STAGE_BYTES;

    // fragment buffers: [0]=slice0, [1]=slice1 (fixed roles)
    uint32_t ar[2][2][4];   // [slice][mt][reg]
    uint32_t br[2][4][4];   // [slice][npair][reg]

    // ---- preload slice0 fragments of stage 0 ----
    CP_WAIT(3);            // stage 0 arrived (own thread)
    __syncthreads();       // visible to all
    ldsm4(ar[0][0], aLane + bufC);
    ldsm4(ar[0][1], aLane + bufC + 16 * ROW_STRIDE);
    #pragma unroll
    for (int p = 0; p < 4; p++)
        ldsm4(br[0][p], bLane + bufC + p * (16 * ROW_STRIDE));

    // ---- main loop (cross-barrier fragment pipeline, reordered body) ----
    #pragma unroll 1
    for (int s = 0; s < KTILES; s++) {
        // groups committed so far: 4 + s; all but 2 done -> stages 0..s+1 ready
        CP_WAIT(2);
        __syncthreads();   // stage s+1 now globally visible; buffer (s-1)%5 free

        // 1) latency-critical: prefetch slice1 of stage s FIRST
        {
            const uint32_t o = bufC + 32;
            ldsm4(ar[1][0], aLane + o);
            ldsm4(ar[1][1], aLane + o + 16 * ROW_STRIDE);
            #pragma unroll
            for (int p = 0; p < 4; p++)
                ldsm4(br[1][p], bLane + o + p * (16 * ROW_STRIDE));
        }

        // 2) mma slice0 (fragments preloaded last iteration) — covers ldsm + cp
        #pragma unroll
        for (int mt = 0; mt < 2; mt++)
            #pragma unroll
            for (int nt = 0; nt < 8; nt++)
                mma16816(acc[mt][nt], ar[0][mt],
                         br[0][nt >> 1][(nt & 1) * 2],
                         br[0][nt >> 1][(nt & 1) * 2 + 1]);

        // 3) bulk: issue cp for stage s+4 into buffer (s-1)%5 (slack ~2 bodies)
        const int ls = s + STAGES - 1;
        if (ls < KTILES) {
            const int k0 = ls * BK;
            const uint32_t st = sb + bufL;
            cp16(st + sA0, X + aOff0 + k0);
            cp16(st + sA1, X + aOff1 + k0);
            cp16(st + TILE_BYTES + sA0, W + bOff0 + k0);
            cp16(st + TILE_BYTES + sA1, W + bOff1 + k0);
        }
        CP_COMMIT();

        // 4) prefetch slice0 of stage s+1 (visible since this iter's barrier;
        //    its buffer is not rewritten until iter s+2 -> safe)
        uint32_t bufN = bufC + STAGE_BYTES;
        if (bufN == SMEM_TOTAL) bufN = 0;
        if (s + 1 < KTILES) {
            ldsm4(ar[0][0], aLane + bufN);
            ldsm4(ar[0][1], aLane + bufN + 16 * ROW_STRIDE);
            #pragma unroll
            for (int p = 0; p < 4; p++)
                ldsm4(br[0][p], bLane + bufN + p * (16 * ROW_STRIDE));
        }

        // 5) mma slice1
        #pragma unroll
        for (int mt = 0; mt < 2; mt++)
            #pragma unroll
            for (int nt = 0; nt < 8; nt++)
                mma16816(acc[mt][nt], ar[1][mt],
                         br[1][nt >> 1][(nt & 1) * 2],
                         br[1][nt >> 1][(nt & 1) * 2 + 1]);

        bufC = bufN;
        bufL += STAGE_BYTES; if (bufL == SMEM_TOTAL) bufL = 0;
    }

    // ---- epilogue: direct stores + bias ----
    const int g = lane >> 2;
    const int t = lane & 3;
    #pragma unroll
    for (int mt = 0; mt < 2; mt++) {
        const int row0 = bm + warpM * 32 + mt * 16 + g;
        #pragma unroll
        for (int nt = 0; nt < 8; nt++) {
            const int col = bn + warpN * 64 + nt * 8 + 2 * t;
            const float2 b2 = *(const float2*)(bias + col);
            float2 o0, o1;
            o0.x = acc[mt][nt][0] + b2.x;
            o0.y = acc[mt][nt][1] + b2.y;
            o1.x = acc[mt][nt][2] + b2.x;
            o1.y = acc[mt][nt][3] + b2.y;
            *(float2*)(out + (size_t)row0 * N_DIM + col)       = o0;
            *(float2*)(out + (size_t)(row0 + 8) * N_DIM + col) = o1;
        }
    }
}

// ---------------- host ----------------
extern "C" void kernel_launch(void* const* d_in, const int* in_sizes, int n_in,
                              void* d_out, int out_size)
{
    const float* x    = (const float*)d_in[0];   // [M, K]
    const float* wr   = (const float*)d_in[1];   // [N, K]
    // d_in[2] = weight_imag: algebraically dead
    const float* bias = (const float*)d_in[3];   // [N]
    float* out = (float*)d_out;

    void *p_xh, *p_wh;
    cudaGetSymbolAddress(&p_xh, g_xh);
    cudaGetSymbolAddress(&p_wh, g_wh);

    const int nblocks_prep = (int)((NX16 + NW16) / 256);
    to_fp16_fused<<<nblocks_prep, 256>>>(
        (const float4*)x, (uint4*)p_xh,
        (const float4*)wr, (uint4*)p_wh);

    cudaFuncSetAttribute(qgemm_fp16, cudaFuncAttributeMaxDynamicSharedMemorySize,
                         SMEM_TOTAL);

    const int nblocks = (M_DIM / BM) * (N_DIM / BN);   // 2048
    qgemm_fp16<<<nblocks, 256, SMEM_TOTAL>>>(
        (const __half*)p_xh, (const __half*)p_wh, bias, out);
}